// round 14
// baseline (speedup 1.0000x reference)
#include <cuda_runtime.h>
#include <cuda.h>
#include <cstdint>

// ============================================================================
// Problem constants
// ============================================================================
#define NN      8192
#define DD      128

// GEMM: hi plane s8 m16n8k32 + lo plane s4 m16n8k64
// CTA tile 128x128, 16 warps (4m x 4n), warp tile 32x32, BK=128
#define BM      128
#define BN      128
#define BK      128
#define STAGES  3
#define KSPLIT  2
#define KCHUNK  (NN / KSPLIT)          // 4096
#define NKT     (KCHUNK / BK)          // 32 K iterations per CTA
#define GTHREADS 512                   // 16 warps

// SMEM row strides (bytes): s8 tiles 128B data + 16 pad; s4 tiles 64B + 16 pad
#define RS8     144
#define RS4     80
#define A8_BYTES  (BM * RS8)                   // 18432
#define BH_BYTES  (BN * RS8)                   // 18432
#define A4_BYTES  (BM * RS4)                   // 10240
#define BL_BYTES  (BN * RS4)                   // 10240
#define OFF_BH    A8_BYTES
#define OFF_A4    (A8_BYTES + BH_BYTES)
#define OFF_BL    (OFF_A4 + A4_BYTES)
#define STAGE_BYTES (OFF_BL + BL_BYTES)        // 57344
#define SMEM_TOTAL  (STAGES * STAGE_BYTES)     // 172032 (1 CTA/SM)

// ============================================================================
// Scratch (device globals; allocation-free)
// ============================================================================
__device__ __align__(1024) float  g_h[NN * DD];
__device__ __align__(1024) float  g_g[NN * DD];
__device__ __align__(1024) int8_t g_A8[(size_t)NN * NN];
__device__ __align__(1024) uint8_t g_A4[(size_t)NN * NN / 2];
__device__ __align__(1024) int8_t g_hi[(size_t)DD * NN];
__device__ __align__(1024) uint8_t g_lo4[(size_t)DD * NN / 2];
__device__ __align__(1024) float  g_p[KSPLIT][NN * DD];
__device__ __align__(128)  float  g_d[NN];
__device__ __align__(128)  float  g_e[NN];
__device__ __align__(128)  unsigned int g_smax[DD];   // colmax |g| as uint bits

// ============================================================================
// PTX helpers
// ============================================================================
__device__ __forceinline__ uint32_t smem_u32(const void* p) {
    uint32_t a;
    asm("{ .reg .u64 t; cvta.to.shared.u64 t, %1; cvt.u32.u64 %0, t; }" : "=r"(a) : "l"(p));
    return a;
}

__device__ __forceinline__ void cp16(uint32_t dst, const void* src) {
    asm volatile("cp.async.cg.shared.global [%0], [%1], 16;" :: "r"(dst), "l"(src));
}

#define CP_COMMIT()  asm volatile("cp.async.commit_group;" ::: "memory")
#define CP_WAIT(n)   asm volatile("cp.async.wait_group %0;" :: "n"(n) : "memory")

// ldmatrix x4: 4 tiles of 8 rows x 16 bytes (dtype-agnostic byte mover)
__device__ __forceinline__ void ldsm_x4(uint32_t* r, uint32_t addr) {
    asm volatile("ldmatrix.sync.aligned.m8n8.x4.shared.b16 {%0,%1,%2,%3}, [%4];"
                 : "=r"(r[0]), "=r"(r[1]), "=r"(r[2]), "=r"(r[3]) : "r"(addr));
}

__device__ __forceinline__ void imma8(int* c, const uint32_t* a, const uint32_t* b) {
    asm volatile(
        "mma.sync.aligned.m16n8k32.row.col.s32.s8.s8.s32 "
        "{%0,%1,%2,%3}, {%4,%5,%6,%7}, {%8,%9}, {%0,%1,%2,%3};"
        : "+r"(c[0]), "+r"(c[1]), "+r"(c[2]), "+r"(c[3])
        : "r"(a[0]), "r"(a[1]), "r"(a[2]), "r"(a[3]), "r"(b[0]), "r"(b[1]));
}

__device__ __forceinline__ void imma4(int* c, const uint32_t* a, const uint32_t* b) {
    asm volatile(
        "mma.sync.aligned.m16n8k64.row.col.s32.s4.s4.s32 "
        "{%0,%1,%2,%3}, {%4,%5,%6,%7}, {%8,%9}, {%0,%1,%2,%3};"
        : "+r"(c[0]), "+r"(c[1]), "+r"(c[2]), "+r"(c[3])
        : "r"(a[0]), "r"(a[1]), "r"(a[2]), "r"(a[3]), "r"(b[0]), "r"(b[1]));
}

// ============================================================================
// K1 (fused): blocks 0..255 -> h = x @ W + b ; blocks 256.. -> rowsum + A8 + A4
// ============================================================================
__global__ void __launch_bounds__(256) pre_kernel(const float* __restrict__ A,
                                                  const float* __restrict__ x,
                                                  const float* __restrict__ W,
                                                  const float* __restrict__ bias) {
    __shared__ float xs[32][128];
    __shared__ float red[8];
    const int tid = threadIdx.x;

    if (blockIdx.x < 256) {
        const int r0 = blockIdx.x * 32;
        const float4* xsrc = (const float4*)(x + (size_t)r0 * DD);
        float4* xdst = (float4*)&xs[0][0];
        for (int idx = tid; idx < 32 * 32; idx += 256) xdst[idx] = xsrc[idx];
        __syncthreads();

        const int n = tid & 127;
        const int rbase = (tid >> 7) * 16;
        const float b = bias[n];
        float acc[16];
#pragma unroll
        for (int r = 0; r < 16; r++) acc[r] = b;
        for (int k = 0; k < 128; k++) {
            float w = W[k * DD + n];
#pragma unroll
            for (int r = 0; r < 16; r++) acc[r] = fmaf(xs[rbase + r][k], w, acc[r]);
        }
#pragma unroll
        for (int r = 0; r < 16; r++) g_h[(size_t)(r0 + rbase + r) * DD + n] = acc[r];
    } else {
        // rowsum + int8 + packed int4 conversion of one row (MLP=8)
        const int i = blockIdx.x - 256;
        const float4* row = (const float4*)(A + (size_t)i * NN);
        char4* a8row = (char4*)(g_A8 + (size_t)i * NN);
        unsigned short* a4row = (unsigned short*)(g_A4 + (size_t)i * (NN / 2));
        float4 v[8];
#pragma unroll
        for (int j = 0; j < 8; j++) v[j] = row[tid + j * 256];
        float s = 0.f;
#pragma unroll
        for (int j = 0; j < 8; j++) {
            s += (v[j].x + v[j].y) + (v[j].z + v[j].w);
            int ix = (int)v[j].x, iy = (int)v[j].y, iz = (int)v[j].z, iw = (int)v[j].w;
            char4 q;
            q.x = (char)ix; q.y = (char)iy; q.z = (char)iz; q.w = (char)iw;
            a8row[tid + j * 256] = q;
            a4row[tid + j * 256] = (unsigned short)(ix | (iy << 4) | (iz << 8) | (iw << 12));
        }
#pragma unroll
        for (int o = 16; o; o >>= 1) s += __shfl_down_sync(0xffffffffu, s, o);
        if ((tid & 31) == 0) red[tid >> 5] = s;
        __syncthreads();
        if (tid == 0) {
            float tot = 0.f;
#pragma unroll
            for (int w = 0; w < 8; w++) tot += red[w];
            float aii = A[(size_t)i * NN + i];
            tot = tot - aii + 1.0f;
            float di = rsqrtf(tot);
            g_d[i] = di;
            g_e[i] = di * (1.0f - aii);
        }
    }
}

// ============================================================================
// K2: g = d*h ; column max |g| -> g_smax
// ============================================================================
__global__ void __launch_bounds__(256) scale_colmax_kernel() {
    __shared__ float sm[256];
    const int tid = threadIdx.x;
    const int col = tid & 127;
    const int half = tid >> 7;
    const int ibase = blockIdx.x * 64 + half * 32;
    float m = 0.f;
#pragma unroll 4
    for (int r = 0; r < 32; r++) {
        int i = ibase + r;
        float v = g_h[(size_t)i * DD + col] * g_d[i];
        g_g[(size_t)i * DD + col] = v;
        m = fmaxf(m, fabsf(v));
    }
    sm[tid] = m;
    __syncthreads();
    if (tid < 128)
        atomicMax(&g_smax[col], __float_as_uint(fmaxf(sm[tid], sm[tid + 128])));
}

// ============================================================================
// K3: quantize + transpose: g -> hi (s8) and lo4 (packed s4, scale 14)
// ============================================================================
__global__ void __launch_bounds__(256) quant_transpose_kernel() {
    __shared__ float t[32][33];
    const int i0 = blockIdx.x * 32;
    const int n0 = blockIdx.y * 32;
    const int tx = threadIdx.x, ty = threadIdx.y;

    for (int r = ty; r < 32; r += 8)
        t[r][tx] = g_g[(size_t)(i0 + r) * DD + n0 + tx];
    __syncthreads();
    for (int r = ty; r < 32; r += 8) {
        int n = n0 + r;
        float inv = 127.f / __uint_as_float(g_smax[n]);
        float q = t[tx][r] * inv;
        float hi = rintf(q);
        hi = fminf(fmaxf(hi, -127.f), 127.f);
        float lo = rintf((q - hi) * 14.f);
        lo = fminf(fmaxf(lo, -7.f), 7.f);
        g_hi[(size_t)n * NN + i0 + tx] = (int8_t)hi;
        int nib = ((int)lo) & 0xF;
        int up = __shfl_down_sync(0xffffffffu, nib, 1);
        if ((tx & 1) == 0)
            g_lo4[(size_t)n * (NN / 2) + (i0 + tx) / 2] = (uint8_t)(nib | (up << 4));
    }
}

// ============================================================================
// K4: partial = fs_n * (A8 @ hi + (A4 @ lo4)/14)  per K-split
//   CTA 128x128, 16 warps (4m x 4n), warp tile 32x32, BK=128,
//   hi: 4x m16n8k32 s8; lo: 2x m16n8k64 s4. 3-stage cp.async, 1 CTA/SM.
// ============================================================================
__global__ void __launch_bounds__(GTHREADS, 1) gcn_gemm()
{
    extern __shared__ char smem[];
    const int tid = threadIdx.x;
    const int wid = tid >> 5;
    const int lane = tid & 31;
    const int gid = lane >> 2;
    const int tg  = lane & 3;
    const int m0 = blockIdx.x * BM;
    const int split = blockIdx.y;
    const int kbase = split * KCHUNK;
    float* __restrict__ part = g_p[split];

    const int mwb = (wid & 3) * 32;     // 4 warps along M
    const int nwb = (wid >> 2) * 32;    // 4 warps along N

    const uint32_t smem_base = smem_u32(smem);

    const int l7  = lane & 7;
    const int l8  = (lane >> 3) & 1;
    const int l16 = (lane >> 4) & 1;
    // s8 tiles
    const uint32_t a8_off0 = (uint32_t)((mwb + l7 + l8 * 8) * RS8 + l16 * 16);
    const uint32_t a8_off1 = a8_off0 + 16u * RS8;
    const uint32_t bh_off0 = (uint32_t)((nwb + l7 + l16 * 8) * RS8 + l8 * 16) + OFF_BH;
    const uint32_t bh_off1 = bh_off0 + 16u * RS8;
    // s4 tiles (64 data bytes per row)
    const uint32_t a4_off0 = (uint32_t)((mwb + l7 + l8 * 8) * RS4 + l16 * 16) + OFF_A4;
    const uint32_t a4_off1 = a4_off0 + 16u * RS4;
    const uint32_t bl_off0 = (uint32_t)((nwb + l7 + l16 * 8) * RS4 + l8 * 16) + OFF_BL;
    const uint32_t bl_off1 = bl_off0 + 16u * RS4;

    // ---- cp.async fill: 3072 x 16B (A8 1024, BH 1024, A4 512, BL4 512) ----
    auto issue_stage = [&](int kt, int slot) {
        const int k0 = kbase + kt * BK;
        const uint32_t st = smem_base + (uint32_t)slot * STAGE_BYTES;
#pragma unroll
        for (int j = 0; j < 6; j++) {
            int c = tid + j * GTHREADS;
            if (c < 1024) {
                int r = c >> 3, c8 = c & 7;
                cp16(st + (uint32_t)(r * RS8 + c8 * 16),
                     g_A8 + (size_t)(m0 + r) * NN + k0 + c8 * 16);
            } else if (c < 2048) {
                int r = (c - 1024) >> 3, c8 = c & 7;
                cp16(st + OFF_BH + (uint32_t)(r * RS8 + c8 * 16),
                     g_hi + (size_t)r * NN + k0 + c8 * 16);
            } else if (c < 2560) {
                int cc = c - 2048;
                int r = cc >> 2, c4 = cc & 3;
                cp16(st + OFF_A4 + (uint32_t)(r * RS4 + c4 * 16),
                     g_A4 + (size_t)(m0 + r) * (NN / 2) + k0 / 2 + c4 * 16);
            } else {
                int cc = c - 2560;
                int r = cc >> 2, c4 = cc & 3;
                cp16(st + OFF_BL + (uint32_t)(r * RS4 + c4 * 16),
                     g_lo4 + (size_t)r * (NN / 2) + k0 / 2 + c4 * 16);
            }
        }
    };

    int ch[2][4][4], cl[2][4][4];
#pragma unroll
    for (int mf = 0; mf < 2; mf++)
#pragma unroll
        for (int nf = 0; nf < 4; nf++)
#pragma unroll
            for (int q = 0; q < 4; q++) { ch[mf][nf][q] = 0; cl[mf][nf][q] = 0; }

#pragma unroll
    for (int s = 0; s < STAGES - 1; s++) {
        issue_stage(s, s);
        CP_COMMIT();
    }

    int slot_r = 0;
    int slot_w = STAGES - 1;

    for (int kt = 0; kt < NKT; kt++) {
        CP_WAIT(STAGES - 2);
        __syncthreads();

        int nxt = kt + STAGES - 1;
        if (nxt < NKT) issue_stage(nxt, slot_w);
        CP_COMMIT();
        if (++slot_w == STAGES) slot_w = 0;

        const uint32_t stg = smem_base + (uint32_t)slot_r * STAGE_BYTES;
        if (++slot_r == STAGES) slot_r = 0;

        // ---- hi plane: 4 x k32 (s8) ----
#pragma unroll
        for (int ks = 0; ks < 4; ks++) {
            const uint32_t ko = (uint32_t)ks * 32u;
            uint32_t a0[4], a1[4], bh[8];
            ldsm_x4(a0, stg + a8_off0 + ko);
            ldsm_x4(a1, stg + a8_off1 + ko);
            ldsm_x4(bh,     stg + bh_off0 + ko);
            ldsm_x4(bh + 4, stg + bh_off1 + ko);
#pragma unroll
            for (int nf = 0; nf < 4; nf++) {
                imma8(ch[0][nf], a0, bh + nf * 2);
                imma8(ch[1][nf], a1, bh + nf * 2);
            }
        }
        // ---- lo plane: 2 x k64 (s4) ----
#pragma unroll
        for (int ks = 0; ks < 2; ks++) {
            const uint32_t ko = (uint32_t)ks * 32u;    // 64 nibbles = 32 bytes
            uint32_t a0[4], a1[4], bl[8];
            ldsm_x4(a0, stg + a4_off0 + ko);
            ldsm_x4(a1, stg + a4_off1 + ko);
            ldsm_x4(bl,     stg + bl_off0 + ko);
            ldsm_x4(bl + 4, stg + bl_off1 + ko);
#pragma unroll
            for (int nf = 0; nf < 4; nf++) {
                imma4(cl[0][nf], a0, bl + nf * 2);
                imma4(cl[1][nf], a1, bl + nf * 2);
            }
        }
    }

    // -------- epilogue: p = fs_n * (S_hi + S_lo/14), store f32 partial --------
    const float inv14 = 1.f / 14.f;
#pragma unroll
    for (int mf = 0; mf < 2; mf++) {
        int i0r = m0 + mwb + mf * 16 + gid;
        int i1r = i0r + 8;
#pragma unroll
        for (int nf = 0; nf < 4; nf++) {
            int n = nwb + nf * 8 + tg * 2;
            float fs0 = __uint_as_float(g_smax[n])     * (1.f / 127.f);
            float fs1 = __uint_as_float(g_smax[n + 1]) * (1.f / 127.f);
            float2 p0, p1;
            p0.x = fs0 * ((float)ch[mf][nf][0] + (float)cl[mf][nf][0] * inv14);
            p0.y = fs1 * ((float)ch[mf][nf][1] + (float)cl[mf][nf][1] * inv14);
            p1.x = fs0 * ((float)ch[mf][nf][2] + (float)cl[mf][nf][2] * inv14);
            p1.y = fs1 * ((float)ch[mf][nf][3] + (float)cl[mf][nf][3] * inv14);
            *(float2*)(part + (size_t)i0r * DD + n) = p0;
            *(float2*)(part + (size_t)i1r * DD + n) = p1;
        }
    }
}

// ============================================================================
// K5: out = d * (p0 + p1) + e * g
// ============================================================================
__global__ void __launch_bounds__(256) combine_kernel(float* __restrict__ out) {
    const int idx = blockIdx.x * 256 + threadIdx.x;      // float4 index
    const int i = (idx * 4) / DD;
    const float d = g_d[i], e = g_e[i];
    const float4 p0 = ((const float4*)g_p[0])[idx];
    const float4 p1 = ((const float4*)g_p[1])[idx];
    const float4 gv = ((const float4*)g_g)[idx];
    float4 o;
    o.x = d * (p0.x + p1.x) + e * gv.x;
    o.y = d * (p0.y + p1.y) + e * gv.y;
    o.z = d * (p0.z + p1.z) + e * gv.z;
    o.w = d * (p0.w + p1.w) + e * gv.w;
    ((float4*)out)[idx] = o;
}

// ============================================================================
// Host side
// ============================================================================
extern "C" void kernel_launch(void* const* d_in, const int* in_sizes, int n_in,
                              void* d_out, int out_size) {
    const float* A    = (const float*)d_in[0];
    const float* x    = (const float*)d_in[1];
    const float* W    = (const float*)d_in[2];
    const float* bias = (const float*)d_in[3];
    float* out = (float*)d_out;

    cudaFuncSetAttribute(gcn_gemm, cudaFuncAttributeMaxDynamicSharedMemorySize, SMEM_TOTAL);

    pre_kernel<<<NN + 256, 256>>>(A, x, W, bias);
    scale_colmax_kernel<<<NN / 64, 256>>>();
    quant_transpose_kernel<<<dim3(NN / 32, DD / 32), dim3(32, 8)>>>();
    gcn_gemm<<<dim3(NN / BM, KSPLIT), GTHREADS, SMEM_TOTAL>>>();
    combine_kernel<<<(NN * DD / 4) / 256, 256>>>(out);
}

// round 15
// speedup vs baseline: 3.5946x; 3.5946x over previous
#include <cuda_runtime.h>
#include <cuda.h>
#include <cstdint>

// ============================================================================
// Problem constants
// ============================================================================
#define NN      8192
#define DD      128

// GEMM config: dual-plane int8 mma.sync m16n8k32, both planes per CTA
// CTA tile 128x128, 16 warps (4m x 4n), warp tile 32x32, BK=128
#define BM      128
#define BN      128
#define BK      128
#define STAGES  3
#define KSPLIT  4
#define KCHUNK  (NN / KSPLIT)          // 2048
#define NKT     (KCHUNK / BK)          // 16 K iterations per CTA
#define GTHREADS 512                   // 16 warps

// SMEM: rows of 128 data bytes + 16 pad (conflict-free ldmatrix, 16B aligned)
#define RSTRIDE 144
#define A_BYTES   (BM * RSTRIDE)               // 18432
#define BP_BYTES  (BN * RSTRIDE)               // 18432 per plane
#define BH_OFF    A_BYTES
#define BL_OFF    (A_BYTES + BP_BYTES)
#define STAGE_BYTES (A_BYTES + 2 * BP_BYTES)   // 55296
#define SMEM_TOTAL  (STAGES * STAGE_BYTES)     // 165888 (1 CTA/SM)

// ============================================================================
// Scratch (device globals; allocation-free)
// ============================================================================
__device__ __align__(1024) float  g_h[NN * DD];
__device__ __align__(1024) int8_t g_A8[(size_t)NN * NN];
__device__ __align__(1024) int8_t g_hi[(size_t)DD * NN];
__device__ __align__(1024) int8_t g_lo[(size_t)DD * NN];
__device__ __align__(1024) float  g_p[KSPLIT][NN * DD];
__device__ __align__(128)  float  g_d[NN];
__device__ __align__(128)  float  g_e2[NN];          // d^2 * (1 - aii)
__device__ __align__(128)  unsigned int g_smax[DD];  // colmax |d*h| as uint bits

// ============================================================================
// PTX helpers
// ============================================================================
__device__ __forceinline__ uint32_t smem_u32(const void* p) {
    uint32_t a;
    asm("{ .reg .u64 t; cvta.to.shared.u64 t, %1; cvt.u32.u64 %0, t; }" : "=r"(a) : "l"(p));
    return a;
}

__device__ __forceinline__ void cp16(uint32_t dst, const void* src) {
    asm volatile("cp.async.cg.shared.global [%0], [%1], 16;" :: "r"(dst), "l"(src));
}

#define CP_COMMIT()  asm volatile("cp.async.commit_group;" ::: "memory")
#define CP_WAIT(n)   asm volatile("cp.async.wait_group %0;" :: "n"(n) : "memory")

// ldmatrix x4: 4 tiles of 8 rows x 16 bytes
__device__ __forceinline__ void ldsm_x4(uint32_t* r, uint32_t addr) {
    asm volatile("ldmatrix.sync.aligned.m8n8.x4.shared.b16 {%0,%1,%2,%3}, [%4];"
                 : "=r"(r[0]), "=r"(r[1]), "=r"(r[2]), "=r"(r[3]) : "r"(addr));
}

__device__ __forceinline__ void imma(int* c, const uint32_t* a, const uint32_t* b) {
    asm volatile(
        "mma.sync.aligned.m16n8k32.row.col.s32.s8.s8.s32 "
        "{%0,%1,%2,%3}, {%4,%5,%6,%7}, {%8,%9}, {%0,%1,%2,%3};"
        : "+r"(c[0]), "+r"(c[1]), "+r"(c[2]), "+r"(c[3])
        : "r"(a[0]), "r"(a[1]), "r"(a[2]), "r"(a[3]), "r"(b[0]), "r"(b[1]));
}

// ============================================================================
// K1 (fused): blocks 0..255 -> h = x @ W + b ; blocks 256.. -> rowsum(A) + A8
// ============================================================================
__global__ void __launch_bounds__(256) pre_kernel(const float* __restrict__ A,
                                                  const float* __restrict__ x,
                                                  const float* __restrict__ W,
                                                  const float* __restrict__ bias) {
    __shared__ float xs[32][128];
    __shared__ float red[8];
    const int tid = threadIdx.x;

    if (blockIdx.x < 256) {
        const int r0 = blockIdx.x * 32;
        const float4* xsrc = (const float4*)(x + (size_t)r0 * DD);
        float4* xdst = (float4*)&xs[0][0];
        for (int idx = tid; idx < 32 * 32; idx += 256) xdst[idx] = xsrc[idx];
        __syncthreads();

        const int n = tid & 127;
        const int rbase = (tid >> 7) * 16;
        const float b = bias[n];
        float acc[16];
#pragma unroll
        for (int r = 0; r < 16; r++) acc[r] = b;
        for (int k = 0; k < 128; k++) {
            float w = W[k * DD + n];
#pragma unroll
            for (int r = 0; r < 16; r++) acc[r] = fmaf(xs[rbase + r][k], w, acc[r]);
        }
#pragma unroll
        for (int r = 0; r < 16; r++) g_h[(size_t)(r0 + rbase + r) * DD + n] = acc[r];
    } else {
        // rowsum + int8 conversion of one row; each thread: 2 groups of
        // 4 consecutive float4 loads -> one packed 16-byte int8 store.
        const int i = blockIdx.x - 256;
        const float4* row = (const float4*)(A + (size_t)i * NN);
        uint4* a8row = (uint4*)(g_A8 + (size_t)i * NN);
        float s = 0.f;
#pragma unroll
        for (int gblk = 0; gblk < 2; gblk++) {
            const int base = gblk * 1024 + tid * 4;
            float4 v[4];
#pragma unroll
            for (int j = 0; j < 4; j++) v[j] = row[base + j];
            uint32_t pk[4];
#pragma unroll
            for (int j = 0; j < 4; j++) {
                s += (v[j].x + v[j].y) + (v[j].z + v[j].w);
                pk[j] = (uint32_t)(uint8_t)(int)v[j].x
                      | ((uint32_t)(uint8_t)(int)v[j].y << 8)
                      | ((uint32_t)(uint8_t)(int)v[j].z << 16)
                      | ((uint32_t)(uint8_t)(int)v[j].w << 24);
            }
            uint4 q;
            q.x = pk[0]; q.y = pk[1]; q.z = pk[2]; q.w = pk[3];
            a8row[gblk * 256 + tid] = q;
        }
#pragma unroll
        for (int o = 16; o; o >>= 1) s += __shfl_down_sync(0xffffffffu, s, o);
        if ((tid & 31) == 0) red[tid >> 5] = s;
        __syncthreads();
        if (tid == 0) {
            float tot = 0.f;
#pragma unroll
            for (int w = 0; w < 8; w++) tot += red[w];
            float aii = A[(size_t)i * NN + i];
            tot = tot - aii + 1.0f;
            float di = rsqrtf(tot);
            g_d[i] = di;
            g_e2[i] = di * di * (1.0f - aii);
        }
    }
}

// ============================================================================
// K2: column max |d*h| -> g_smax (atomicMax on float bits, values >= 0)
// ============================================================================
__global__ void __launch_bounds__(256) colmax_kernel() {
    __shared__ float sm[256];
    const int tid = threadIdx.x;
    const int col = tid & 127;
    const int half = tid >> 7;
    const int ibase = blockIdx.x * 64 + half * 32;
    float m = 0.f;
#pragma unroll 4
    for (int r = 0; r < 32; r++) {
        int i = ibase + r;
        float v = g_h[(size_t)i * DD + col] * g_d[i];
        m = fmaxf(m, fabsf(v));
    }
    sm[tid] = m;
    __syncthreads();
    if (tid < 128)
        atomicMax(&g_smax[col], __float_as_uint(fmaxf(sm[tid], sm[tid + 128])));
}

// ============================================================================
// K3: quantize + transpose: d*h -> hi/lo planes [n][i] int8
// ============================================================================
__global__ void __launch_bounds__(256) quant_transpose_kernel() {
    __shared__ float t[32][33];
    const int i0 = blockIdx.x * 32;
    const int n0 = blockIdx.y * 32;
    const int tx = threadIdx.x, ty = threadIdx.y;

    for (int r = ty; r < 32; r += 8) {
        int i = i0 + r;
        t[r][tx] = g_h[(size_t)i * DD + n0 + tx] * g_d[i];
    }
    __syncthreads();
    for (int r = ty; r < 32; r += 8) {
        int n = n0 + r;
        float inv = 127.f / __uint_as_float(g_smax[n]);
        float q = t[tx][r] * inv;
        float hi = rintf(q);
        hi = fminf(fmaxf(hi, -127.f), 127.f);
        float lo = rintf((q - hi) * 254.f);
        lo = fminf(fmaxf(lo, -127.f), 127.f);
        g_hi[(size_t)n * NN + i0 + tx] = (int8_t)hi;
        g_lo[(size_t)n * NN + i0 + tx] = (int8_t)lo;
    }
}

// ============================================================================
// K4: partial = fs_n * (A8 @ hi + (A8 @ lo)/254)  per K-split
//   CTA 128x128, 16 warps (4m x 4n), warp tile 32x32, BK=128,
//   3-stage cp.async pipeline, 1 CTA/SM.  (R12 configuration)
// ============================================================================
__global__ void __launch_bounds__(GTHREADS, 1) gcn_gemm()
{
    extern __shared__ char smem[];
    const int tid = threadIdx.x;
    const int wid = tid >> 5;
    const int lane = tid & 31;
    const int gid = lane >> 2;
    const int tg  = lane & 3;
    const int m0 = blockIdx.x * BM;
    const int split = blockIdx.y;
    const int kbase = split * KCHUNK;
    float* __restrict__ part = g_p[split];

    const int mwb = (wid & 3) * 32;     // 4 warps along M
    const int nwb = (wid >> 2) * 32;    // 4 warps along N

    const uint32_t smem_base = smem_u32(smem);

    const int l7  = lane & 7;
    const int l8  = (lane >> 3) & 1;
    const int l16 = (lane >> 4) & 1;
    const uint32_t a_off0 = (uint32_t)((mwb + l7 + l8 * 8) * RSTRIDE + l16 * 16);
    const uint32_t a_off1 = a_off0 + 16u * RSTRIDE;
    const uint32_t b_off0 = (uint32_t)((nwb + l7 + l16 * 8) * RSTRIDE + l8 * 16);
    const uint32_t b_off1 = b_off0 + 16u * RSTRIDE;

    // -------- cp.async stage fill: 3072 x 16B (A 1024, Bhi 1024, Blo 1024) ----
    auto issue_stage = [&](int kt, int slot) {
        const int k0 = kbase + kt * BK;
        const uint32_t st = smem_base + (uint32_t)slot * STAGE_BYTES;
#pragma unroll
        for (int j = 0; j < 6; j++) {
            int c = tid + j * GTHREADS;
            int r = (c >> 3) & 127, c8 = c & 7;
            if (c < 1024) {
                cp16(st + (uint32_t)(r * RSTRIDE + c8 * 16),
                     g_A8 + (size_t)(m0 + r) * NN + k0 + c8 * 16);
            } else if (c < 2048) {
                cp16(st + BH_OFF + (uint32_t)(r * RSTRIDE + c8 * 16),
                     g_hi + (size_t)r * NN + k0 + c8 * 16);
            } else {
                cp16(st + BL_OFF + (uint32_t)(r * RSTRIDE + c8 * 16),
                     g_lo + (size_t)r * NN + k0 + c8 * 16);
            }
        }
    };

    int ch[2][4][4], cl[2][4][4];
#pragma unroll
    for (int mf = 0; mf < 2; mf++)
#pragma unroll
        for (int nf = 0; nf < 4; nf++)
#pragma unroll
            for (int q = 0; q < 4; q++) { ch[mf][nf][q] = 0; cl[mf][nf][q] = 0; }

#pragma unroll
    for (int s = 0; s < STAGES - 1; s++) {
        issue_stage(s, s);
        CP_COMMIT();
    }

    int slot_r = 0;
    int slot_w = STAGES - 1;

    for (int kt = 0; kt < NKT; kt++) {
        CP_WAIT(STAGES - 2);
        __syncthreads();

        int nxt = kt + STAGES - 1;
        if (nxt < NKT) issue_stage(nxt, slot_w);
        CP_COMMIT();
        if (++slot_w == STAGES) slot_w = 0;

        const uint32_t stg = smem_base + (uint32_t)slot_r * STAGE_BYTES;
        if (++slot_r == STAGES) slot_r = 0;

#pragma unroll
        for (int ks = 0; ks < 4; ks++) {
            const uint32_t ko = (uint32_t)ks * 32u;    // k32 step = 32 bytes
            uint32_t a0[4], a1[4], bh[8], bl[8];
            ldsm_x4(a0, stg + a_off0 + ko);
            ldsm_x4(a1, stg + a_off1 + ko);
            ldsm_x4(bh,     stg + BH_OFF + b_off0 + ko);   // nf0, nf1
            ldsm_x4(bh + 4, stg + BH_OFF + b_off1 + ko);   // nf2, nf3
            ldsm_x4(bl,     stg + BL_OFF + b_off0 + ko);
            ldsm_x4(bl + 4, stg + BL_OFF + b_off1 + ko);
#pragma unroll
            for (int nf = 0; nf < 4; nf++) {
                imma(ch[0][nf], a0, bh + nf * 2);
                imma(ch[1][nf], a1, bh + nf * 2);
                imma(cl[0][nf], a0, bl + nf * 2);
                imma(cl[1][nf], a1, bl + nf * 2);
            }
        }
    }

    // -------- epilogue: p = fs_n * (S_hi + S_lo/254), store f32 partial --------
    const float inv254 = 1.f / 254.f;
#pragma unroll
    for (int mf = 0; mf < 2; mf++) {
        int i0r = m0 + mwb + mf * 16 + gid;
        int i1r = i0r + 8;
#pragma unroll
        for (int nf = 0; nf < 4; nf++) {
            int n = nwb + nf * 8 + tg * 2;
            float fs0 = __uint_as_float(g_smax[n])     * (1.f / 127.f);
            float fs1 = __uint_as_float(g_smax[n + 1]) * (1.f / 127.f);
            float2 p0, p1;
            p0.x = fs0 * ((float)ch[mf][nf][0] + (float)cl[mf][nf][0] * inv254);
            p0.y = fs1 * ((float)ch[mf][nf][1] + (float)cl[mf][nf][1] * inv254);
            p1.x = fs0 * ((float)ch[mf][nf][2] + (float)cl[mf][nf][2] * inv254);
            p1.y = fs1 * ((float)ch[mf][nf][3] + (float)cl[mf][nf][3] * inv254);
            *(float2*)(part + (size_t)i0r * DD + n) = p0;
            *(float2*)(part + (size_t)i1r * DD + n) = p1;
        }
    }
}

// ============================================================================
// K5: out = d * sum(p[0..KSPLIT-1]) + e2 * h    (e2 = d^2 (1-aii))
// ============================================================================
__global__ void __launch_bounds__(256) combine_kernel(float* __restrict__ out) {
    const int idx = blockIdx.x * 256 + threadIdx.x;      // float4 index
    const int i = (idx * 4) / DD;
    const float d = g_d[i], e2 = g_e2[i];
    float4 s = ((const float4*)g_p[0])[idx];
#pragma unroll
    for (int p = 1; p < KSPLIT; p++) {
        const float4 v = ((const float4*)g_p[p])[idx];
        s.x += v.x; s.y += v.y; s.z += v.z; s.w += v.w;
    }
    const float4 hv = ((const float4*)g_h)[idx];
    float4 o;
    o.x = d * s.x + e2 * hv.x;
    o.y = d * s.y + e2 * hv.y;
    o.z = d * s.z + e2 * hv.z;
    o.w = d * s.w + e2 * hv.w;
    ((float4*)out)[idx] = o;
}

// ============================================================================
// Host side
// ============================================================================
extern "C" void kernel_launch(void* const* d_in, const int* in_sizes, int n_in,
                              void* d_out, int out_size) {
    const float* A    = (const float*)d_in[0];
    const float* x    = (const float*)d_in[1];
    const float* W    = (const float*)d_in[2];
    const float* bias = (const float*)d_in[3];
    float* out = (float*)d_out;

    cudaFuncSetAttribute(gcn_gemm, cudaFuncAttributeMaxDynamicSharedMemorySize, SMEM_TOTAL);

    pre_kernel<<<NN + 256, 256>>>(A, x, W, bias);
    colmax_kernel<<<NN / 64, 256>>>();
    quant_transpose_kernel<<<dim3(NN / 32, DD / 32), dim3(32, 8)>>>();
    gcn_gemm<<<dim3(NN / BM, KSPLIT), GTHREADS, SMEM_TOTAL>>>();
    combine_kernel<<<(NN * DD / 4) / 256, 256>>>(out);
}